// round 3
// baseline (speedup 1.0000x reference)
#include <cuda_runtime.h>
#include <cuda_bf16.h>
#include <cstdint>

// ============================================================================
// InteractionPruning: out[b,i,j] = f_i^T Z_ij f_j,  Z = clip(sig(M)*1.2-0.1,0,1)
// Split: Z = 0.5 + R,  R = clip(0.6*tanh(M/2), -0.5, 0.5)
//   out = 0.5*S_i*S_j (fp32 exact)  +  f_i^T R f_j (bf16 mma.sync HMMA)
// All operands pre-packed in mma.sync fragment order by prep kernels, so the
// main kernel does only conflict-free vector ld.shared + HMMA.
// ============================================================================

#define B_SZ   1024
#define F_SZ   32
#define D_SZ   128
#define NPAIR  496          // F*(F-1)/2
#define NBT    8            // 1024 / 128 batch tiles

// Fragment-image scratch (device globals; runtime allocation forbidden)
// g_FA: A-frag images of feature (F_j):  [bt][f] x (mt8 x ks8 x lane32) uint4  = 32KB/tile
// g_RB: B-frag images of R:              [p]    x (nt16 x ks8 x lane32) uint2  = 32KB/pair
// g_FC: C-epilogue images of F_i:        [bt][f] x (mt8 x nt16 x lane32) uint2 = 32KB/tile
__device__ uint4 g_FA[NBT * F_SZ * 2048];   // 8 MB
__device__ uint4 g_RB[NPAIR * 2048];        // 15.9 MB
__device__ uint4 g_FC[NBT * F_SZ * 2048];   // 8 MB
__device__ float g_S[B_SZ * F_SZ];          // row sums of feature

// ---------------------------------------------------------------------------
// helpers
// ---------------------------------------------------------------------------
__device__ __forceinline__ void decode_pair(int p, int& i, int& j) {
    int jj = (int)((1.0f + sqrtf(1.0f + 8.0f * (float)p)) * 0.5f);
    while (jj * (jj - 1) / 2 > p) --jj;
    while ((jj + 1) * jj / 2 <= p) ++jj;
    j = jj;
    i = p - jj * (jj - 1) / 2;
}

// R = clip(Z,0,1) - 0.5 = clip(0.6*tanh(m/2), -0.5, 0.5)
__device__ __forceinline__ float gate_r(float m) {
    float x = 0.5f * m;
    if (fabsf(m) < 0.04f) {
        return 0.6f * (x - 0.33333334f * x * x * x);   // rel err < 1e-7
    }
    float s = 1.0f / (1.0f + __expf(-m));
    return fminf(fmaxf(1.2f * s - 0.6f, -0.5f), 0.5f);
}

__device__ __forceinline__ uint32_t pack_bf16x2(float a, float b) {
    return (uint32_t)__bfloat16_as_ushort(__float2bfloat16(a)) |
           ((uint32_t)__bfloat16_as_ushort(__float2bfloat16(b)) << 16);
}

__device__ __forceinline__ float2 bf2_to_f2(uint32_t u) {
    __nv_bfloat162 h = *reinterpret_cast<__nv_bfloat162*>(&u);
    return __bfloat1622float2(h);
}

// mma.sync m16n8k16 row.col f32 += bf16*bf16
__device__ __forceinline__ void mma16816(float* c, const uint32_t* a, const uint32_t* b) {
    asm volatile(
        "mma.sync.aligned.m16n8k16.row.col.f32.bf16.bf16.f32 "
        "{%0,%1,%2,%3}, {%4,%5,%6,%7}, {%8,%9}, {%0,%1,%2,%3};"
        : "+f"(c[0]), "+f"(c[1]), "+f"(c[2]), "+f"(c[3])
        : "r"(a[0]), "r"(a[1]), "r"(a[2]), "r"(a[3]), "r"(b[0]), "r"(b[1]));
}

// ---------------------------------------------------------------------------
// Prep kernels — write fragment-order images
// ---------------------------------------------------------------------------

// A-fragments of feature. One thread per (bt,f,mt,ks,lane) -> uint4. 2^19 threads.
// a0=A[r][k0,k0+1] a1=A[r+8][k0..] a2=A[r][k0+8..] a3=A[r+8][k0+8..]
__global__ void prep_FA(const float* __restrict__ feature) {
    int g = blockIdx.x * 256 + threadIdx.x;
    int lane = g & 31, ks = (g >> 5) & 7, mt = (g >> 8) & 7;
    int f = (g >> 11) & 31, bt = g >> 16;
    int b0 = bt * 128 + mt * 16 + (lane >> 2);
    int b1 = b0 + 8;
    int k0 = ks * 16 + (lane & 3) * 2;
    const float2* r0 = reinterpret_cast<const float2*>(feature + ((size_t)(b0 * F_SZ + f) * D_SZ + k0));
    const float2* r1 = reinterpret_cast<const float2*>(feature + ((size_t)(b1 * F_SZ + f) * D_SZ + k0));
    float2 a0 = r0[0], a2 = r0[4];   // +8 floats = +4 float2
    float2 a1 = r1[0], a3 = r1[4];
    uint4 o;
    o.x = pack_bf16x2(a0.x, a0.y);
    o.y = pack_bf16x2(a1.x, a1.y);
    o.z = pack_bf16x2(a2.x, a2.y);
    o.w = pack_bf16x2(a3.x, a3.y);
    g_FA[g] = o;
}

// C-epilogue fragments of feature (F_i). One thread per (bt,f,mt,nt,lane) -> uint2.
// 2^20 threads.  lo={Fi[r][d0],Fi[r][d0+1]}, hi={Fi[r+8][d0],Fi[r+8][d0+1]}
__global__ void prep_FC(const float* __restrict__ feature) {
    int g = blockIdx.x * 256 + threadIdx.x;
    int lane = g & 31, nt = (g >> 5) & 15, mt = (g >> 9) & 7;
    int f = (g >> 12) & 31, bt = g >> 17;
    int b0 = bt * 128 + mt * 16 + (lane >> 2);
    int b1 = b0 + 8;
    int d0 = nt * 8 + (lane & 3) * 2;
    float2 lo = *reinterpret_cast<const float2*>(feature + ((size_t)(b0 * F_SZ + f) * D_SZ + d0));
    float2 hi = *reinterpret_cast<const float2*>(feature + ((size_t)(b1 * F_SZ + f) * D_SZ + d0));
    uint2 o;
    o.x = pack_bf16x2(lo.x, lo.y);
    o.y = pack_bf16x2(hi.x, hi.y);
    reinterpret_cast<uint2*>(g_FC)[g] = o;
}

// B-fragments of R. One thread per (p,nt,ks,lane) -> uint2. 496*4096 threads.
// B[k][n] = R[d=n][e=k];  b0={B[k0][n],B[k0+1][n]}, b1={B[k0+8][n],B[k0+9][n]}
__global__ void prep_RB(const float* __restrict__ matrix) {
    int g = blockIdx.x * 256 + threadIdx.x;
    int lane = g & 31, ks = (g >> 5) & 7, nt = (g >> 8) & 15;
    int p = g >> 12;
    int i, j; decode_pair(p, i, j);
    int d = nt * 8 + (lane >> 2);
    int k0 = ks * 16 + (lane & 3) * 2;
    const float2* src = reinterpret_cast<const float2*>(
        matrix + (((size_t)(i * F_SZ + j) * D_SZ + d) * D_SZ + k0));
    float2 v0 = src[0], v1 = src[4];                 // e=k0,k0+1 and k0+8,k0+9
    uint2 o;
    o.x = pack_bf16x2(gate_r(v0.x), gate_r(v0.y));
    o.y = pack_bf16x2(gate_r(v1.x), gate_r(v1.y));
    reinterpret_cast<uint2*>(g_RB)[g] = o;
}

// Row sums S[b,f] = sum_d feature[b,f,d]; one warp per row.
__global__ void prep_S(const float* __restrict__ feature) {
    int gw = (blockIdx.x * 256 + threadIdx.x) >> 5;
    int lane = threadIdx.x & 31;
    float4 v = reinterpret_cast<const float4*>(feature + (size_t)gw * 128)[lane];
    float s = v.x + v.y + v.z + v.w;
#pragma unroll
    for (int o = 16; o; o >>= 1) s += __shfl_xor_sync(0xffffffffu, s, o);
    if (lane == 0) g_S[gw] = s;
}

__global__ void zero_out(float4* __restrict__ out) {
    out[blockIdx.x * 256 + threadIdx.x] = make_float4(0.f, 0.f, 0.f, 0.f);
}

// ---------------------------------------------------------------------------
// Main kernel: CTA = (pair p, batch tile bt). 4 warps, 32 batch rows each.
//   D[b,d] = sum_e Fj[b,e] * R[d,e]   (HMMA, m=128 n=128 k=128)
//   out[b,i,j] = 0.5*S_i*S_j + sum_d Fi[b,d]*D[b,d]
// SMEM: sA (32KB) | sB (32KB) | sC (32KB) = 96 KB
// ---------------------------------------------------------------------------
__global__ void __launch_bounds__(128) main_mma(float* __restrict__ out) {
    extern __shared__ char sm[];
    uint4* sA = reinterpret_cast<uint4*>(sm);              // [mt8][ks8][lane32] uint4
    uint2* sB = reinterpret_cast<uint2*>(sm + 32768);      // [nt16][ks8][lane32] uint2
    uint2* sC = reinterpret_cast<uint2*>(sm + 65536);      // [mt8][nt16][lane32] uint2

    int tid = threadIdx.x, w = tid >> 5, lane = tid & 31;
    int bx = blockIdx.x;
    int p = bx >> 3, bt = bx & 7;
    int i, j; decode_pair(p, i, j);

    // ---- bulk copy of the three fragment images (each 2048 uint4) ----
    const uint4* gA = g_FA + (size_t)(bt * F_SZ + j) * 2048;
    const uint4* gB = g_RB + (size_t)p * 2048;
    const uint4* gC = g_FC + (size_t)(bt * F_SZ + i) * 2048;
    uint4* s4 = reinterpret_cast<uint4*>(sm);
#pragma unroll
    for (int k = 0; k < 16; k++) s4[tid + 128 * k] = gA[tid + 128 * k];
#pragma unroll
    for (int k = 0; k < 16; k++) s4[2048 + tid + 128 * k] = gB[tid + 128 * k];
#pragma unroll
    for (int k = 0; k < 16; k++) s4[4096 + tid + 128 * k] = gC[tid + 128 * k];
    __syncthreads();

    // ---- load A fragments for this warp's 32 rows (mtiles 2w, 2w+1) ----
    uint32_t Afr[2][8][4];
#pragma unroll
    for (int mt = 0; mt < 2; mt++) {
#pragma unroll
        for (int ks = 0; ks < 8; ks++) {
            uint4 v = sA[((2 * w + mt) * 8 + ks) * 32 + lane];
            Afr[mt][ks][0] = v.x; Afr[mt][ks][1] = v.y;
            Afr[mt][ks][2] = v.z; Afr[mt][ks][3] = v.w;
        }
    }

    float pacc[2][2] = {{0.f, 0.f}, {0.f, 0.f}};

#pragma unroll
    for (int g4 = 0; g4 < 4; g4++) {                // n (=d) in 4 groups of 32
        float acc[2][4][4];
#pragma unroll
        for (int mt = 0; mt < 2; mt++)
#pragma unroll
            for (int nt = 0; nt < 4; nt++)
#pragma unroll
                for (int q = 0; q < 4; q++) acc[mt][nt][q] = 0.f;

#pragma unroll
        for (int ks = 0; ks < 8; ks++) {
            uint32_t Bfr[4][2];
#pragma unroll
            for (int nt = 0; nt < 4; nt++) {
                uint2 v = sB[((g4 * 4 + nt) * 8 + ks) * 32 + lane];
                Bfr[nt][0] = v.x; Bfr[nt][1] = v.y;
            }
#pragma unroll
            for (int mt = 0; mt < 2; mt++)
#pragma unroll
                for (int nt = 0; nt < 4; nt++)
                    mma16816(acc[mt][nt], Afr[mt][ks], Bfr[nt]);
        }

        // ---- group epilogue: dot with Fi fragments ----
#pragma unroll
        for (int mt = 0; mt < 2; mt++) {
#pragma unroll
            for (int nt = 0; nt < 4; nt++) {
                uint2 c = sC[((2 * w + mt) * 16 + (g4 * 4 + nt)) * 32 + lane];
                float2 lo = bf2_to_f2(c.x);
                float2 hi = bf2_to_f2(c.y);
                pacc[mt][0] += acc[mt][nt][0] * lo.x + acc[mt][nt][1] * lo.y;
                pacc[mt][1] += acc[mt][nt][2] * hi.x + acc[mt][nt][3] * hi.y;
            }
        }
    }

    // ---- quad reduce (cols live on lanes sharing lane>>2) ----
#pragma unroll
    for (int mt = 0; mt < 2; mt++)
#pragma unroll
        for (int h = 0; h < 2; h++) {
            pacc[mt][h] += __shfl_xor_sync(0xffffffffu, pacc[mt][h], 1);
            pacc[mt][h] += __shfl_xor_sync(0xffffffffu, pacc[mt][h], 2);
        }

    if ((lane & 3) == 0) {
#pragma unroll
        for (int mt = 0; mt < 2; mt++) {
#pragma unroll
            for (int h = 0; h < 2; h++) {
                int row = (2 * w + mt) * 16 + (lane >> 2) + h * 8;
                int bg = bt * 128 + row;
                float res = 0.5f * g_S[bg * F_SZ + i] * g_S[bg * F_SZ + j] + pacc[mt][h];
                out[(size_t)bg * (F_SZ * F_SZ) + i * F_SZ + j] = res;
            }
        }
    }
}

// ---------------------------------------------------------------------------
extern "C" void kernel_launch(void* const* d_in, const int* in_sizes, int n_in,
                              void* d_out, int out_size) {
    const float* feature = (const float*)d_in[0];   // [1024, 32, 128] f32
    const float* matrix  = (const float*)d_in[1];   // [32, 32, 128, 128] f32
    float* out = (float*)d_out;                     // [1024, 32, 32] f32

    cudaFuncSetAttribute(main_mma, cudaFuncAttributeMaxDynamicSharedMemorySize, 98304);

    prep_FA<<<(NBT * F_SZ * 2048) / 256, 256>>>(feature);        // 2^19 thr
    prep_FC<<<(NBT * F_SZ * 4096) / 256, 256>>>(feature);        // 2^20 thr
    prep_RB<<<(NPAIR * 4096) / 256, 256>>>(matrix);              // 496*4096 thr
    prep_S<<<(B_SZ * F_SZ * 32) / 256, 256>>>(feature);          // 2^20 thr
    zero_out<<<(B_SZ * F_SZ * F_SZ / 4) / 256, 256>>>((float4*)out);
    main_mma<<<NPAIR * NBT, 128, 98304>>>(out);                  // 3968 blocks
}

// round 4
// speedup vs baseline: 1.1845x; 1.1845x over previous
#include <cuda_runtime.h>
#include <cuda_bf16.h>
#include <cstdint>

// ============================================================================
// InteractionPruning: out[b,i,j] = f_i^T Z_ij f_j,  Z = clip(sig(M)*1.2-0.1,0,1)
// Split: Z = 0.5 + R,  R = clip(0.6*tanh(M/2), -0.5, 0.5)
//   out = 0.5*S_i*S_j (fp32 exact)  +  f_i^T R f_j (bf16 mma.sync HMMA)
// v3: prep_FC eliminated (C-frags are sub-words of A-frags), preps merged,
//     main-kernel tile copies via cp.async (LDGSTS), 2 CTAs/SM.
// ============================================================================

#define B_SZ   1024
#define F_SZ   32
#define D_SZ   128
#define NPAIR  496          // F*(F-1)/2
#define NBT    8            // 1024 / 128 batch tiles

// g_FA: A-frag images of feature:  [bt][f] x (mt8 x ks8 x lane32) uint4 = 32KB/tile
// g_RB: B-frag images of R:        [p]    x (nt16 x ks8 x lane32) uint2 = 32KB/pair
__device__ uint4 g_FA[NBT * F_SZ * 2048];   // 8 MB
__device__ uint4 g_RB[NPAIR * 2048];        // 15.9 MB
__device__ float g_S[B_SZ * F_SZ];          // row sums of feature

// ---------------------------------------------------------------------------
// helpers
// ---------------------------------------------------------------------------
__device__ __forceinline__ void decode_pair(int p, int& i, int& j) {
    int jj = (int)((1.0f + sqrtf(1.0f + 8.0f * (float)p)) * 0.5f);
    while (jj * (jj - 1) / 2 > p) --jj;
    while ((jj + 1) * jj / 2 <= p) ++jj;
    j = jj;
    i = p - jj * (jj - 1) / 2;
}

// R = clip(Z,0,1) - 0.5 = clip(0.6*tanh(m/2), -0.5, 0.5)
__device__ __forceinline__ float gate_r(float m) {
    float x = 0.5f * m;
    if (fabsf(m) < 0.04f) {
        return 0.6f * (x - 0.33333334f * x * x * x);   // rel err < 1e-7
    }
    float s = 1.0f / (1.0f + __expf(-m));
    return fminf(fmaxf(1.2f * s - 0.6f, -0.5f), 0.5f);
}

__device__ __forceinline__ uint32_t pack_bf16x2(float a, float b) {
    return (uint32_t)__bfloat16_as_ushort(__float2bfloat16(a)) |
           ((uint32_t)__bfloat16_as_ushort(__float2bfloat16(b)) << 16);
}

__device__ __forceinline__ float2 bf2_to_f2(uint32_t u) {
    __nv_bfloat162 h = *reinterpret_cast<__nv_bfloat162*>(&u);
    return __bfloat1622float2(h);
}

// mma.sync m16n8k16 row.col f32 += bf16*bf16
__device__ __forceinline__ void mma16816(float* c, const uint32_t* a, const uint32_t* b) {
    asm volatile(
        "mma.sync.aligned.m16n8k16.row.col.f32.bf16.bf16.f32 "
        "{%0,%1,%2,%3}, {%4,%5,%6,%7}, {%8,%9}, {%0,%1,%2,%3};"
        : "+f"(c[0]), "+f"(c[1]), "+f"(c[2]), "+f"(c[3])
        : "r"(a[0]), "r"(a[1]), "r"(a[2]), "r"(a[3]), "r"(b[0]), "r"(b[1]));
}

#define CP_ASYNC16(dst_u32, src_ptr) \
    asm volatile("cp.async.cg.shared.global [%0], [%1], 16;" \
                 :: "r"(dst_u32), "l"(src_ptr) : "memory")
#define CP_COMMIT() asm volatile("cp.async.commit_group;" ::: "memory")
#define CP_WAIT_ALL() asm volatile("cp.async.wait_all;" ::: "memory")

// ---------------------------------------------------------------------------
// prep_feat: per block (bt,f,mt): A-fragments + row sums S + zero slice of out
// block = 256 threads (ks8 x lane32); grid = 2048
// frag: a0=F[r][k0,k0+1] a1=F[r+8][k0..] a2=F[r][k0+8..] a3=F[r+8][k0+8..]
// ---------------------------------------------------------------------------
__global__ void __launch_bounds__(256) prep_feat(const float* __restrict__ feature,
                                                 float2* __restrict__ out2) {
    __shared__ float ssum[16];
    int tid = threadIdx.x, bid = blockIdx.x;
    int lane = tid & 31, ks = (tid >> 5) & 7;
    int mt = bid & 7, f = (bid >> 3) & 31, bt = bid >> 8;
    if (tid < 16) ssum[tid] = 0.f;
    __syncthreads();

    int r4 = lane >> 2;
    int b0 = bt * 128 + mt * 16 + r4, b1 = b0 + 8;
    int k0 = ks * 16 + (lane & 3) * 2;
    const float2* r0p = reinterpret_cast<const float2*>(feature + ((size_t)(b0 * F_SZ + f) * D_SZ + k0));
    const float2* r1p = reinterpret_cast<const float2*>(feature + ((size_t)(b1 * F_SZ + f) * D_SZ + k0));
    float2 a0 = r0p[0], a2 = r0p[4];
    float2 a1 = r1p[0], a3 = r1p[4];
    uint4 o;
    o.x = pack_bf16x2(a0.x, a0.y);
    o.y = pack_bf16x2(a1.x, a1.y);
    o.z = pack_bf16x2(a2.x, a2.y);
    o.w = pack_bf16x2(a3.x, a3.y);
    g_FA[(size_t)bid * 256 + tid] = o;

    atomicAdd(&ssum[r4],     a0.x + a0.y + a2.x + a2.y);
    atomicAdd(&ssum[8 + r4], a1.x + a1.y + a3.x + a3.y);

    // zero the output buffer (524288 float2 across 2048x256 threads)
    out2[(size_t)bid * 256 + tid] = make_float2(0.f, 0.f);

    __syncthreads();
    if (tid < 16) {
        int b = bt * 128 + mt * 16 + tid;   // rows 0..15 of this block
        g_S[b * F_SZ + f] = ssum[tid];
    }
}

// ---------------------------------------------------------------------------
// prep_RB: B-fragments of R. One thread per (p,nt,ks,lane) -> uint2.
// B[k][n] = R[d=n][e=k];  b0={B[k0][n],B[k0+1][n]}, b1={B[k0+8][n],B[k0+9][n]}
// ---------------------------------------------------------------------------
__global__ void __launch_bounds__(256) prep_RB(const float* __restrict__ matrix) {
    int g = blockIdx.x * 256 + threadIdx.x;
    int lane = g & 31, ks = (g >> 5) & 7, nt = (g >> 8) & 15;
    int p = g >> 12;
    int i, j; decode_pair(p, i, j);
    int d = nt * 8 + (lane >> 2);
    int k0 = ks * 16 + (lane & 3) * 2;
    const float2* src = reinterpret_cast<const float2*>(
        matrix + (((size_t)(i * F_SZ + j) * D_SZ + d) * D_SZ + k0));
    float2 v0 = src[0], v1 = src[4];
    uint2 o;
    o.x = pack_bf16x2(gate_r(v0.x), gate_r(v0.y));
    o.y = pack_bf16x2(gate_r(v1.x), gate_r(v1.y));
    reinterpret_cast<uint2*>(g_RB)[g] = o;
}

// ---------------------------------------------------------------------------
// Main kernel: CTA = (pair p, batch tile bt). 4 warps, 32 batch rows each.
//   D[b,d] = sum_e Fj[b,e] * R[d,e]   (HMMA, m=128 n=128 k=128)
//   out[b,i,j] = 0.5*S_i*S_j + sum_d Fi[b,d]*D[b,d]
// SMEM: sA (Fj A-frags 32KB) | sB (R B-frags 32KB) | sC (Fi A-frags 32KB)
// ---------------------------------------------------------------------------
__global__ void __launch_bounds__(128, 2) main_mma(float* __restrict__ out) {
    extern __shared__ char sm[];
    int tid = threadIdx.x, w = tid >> 5, lane = tid & 31;
    int bx = blockIdx.x;
    int p = bx >> 3, bt = bx & 7;
    int i, j; decode_pair(p, i, j);

    uint32_t sb = 0;
    asm("{ .reg .u64 t; cvta.to.shared.u64 t, %1; cvt.u32.u64 %0, t; }"
        : "=r"(sb) : "l"(sm));

    const uint4* gA = g_FA + (size_t)(bt * F_SZ + j) * 2048;
    const uint4* gB = g_RB + (size_t)p * 2048;
    const uint4* gC = g_FA + (size_t)(bt * F_SZ + i) * 2048;

#pragma unroll
    for (int k = 0; k < 16; k++)
        CP_ASYNC16(sb + (uint32_t)(tid + 128 * k) * 16, (const void*)(gA + tid + 128 * k));
#pragma unroll
    for (int k = 0; k < 16; k++)
        CP_ASYNC16(sb + 32768u + (uint32_t)(tid + 128 * k) * 16, (const void*)(gB + tid + 128 * k));
#pragma unroll
    for (int k = 0; k < 16; k++)
        CP_ASYNC16(sb + 65536u + (uint32_t)(tid + 128 * k) * 16, (const void*)(gC + tid + 128 * k));
    CP_COMMIT();
    CP_WAIT_ALL();
    __syncthreads();

    const uint4* sA = reinterpret_cast<const uint4*>(sm);           // [mt8][ks8][lane32]
    const uint2* sB = reinterpret_cast<const uint2*>(sm + 32768);   // [nt16][ks8][lane32]
    const uint4* sC = reinterpret_cast<const uint4*>(sm + 65536);   // [mt8][ks8][lane32]

    // ---- load A fragments for this warp's 32 rows (mtiles 2w, 2w+1) ----
    uint32_t Afr[2][8][4];
#pragma unroll
    for (int mt = 0; mt < 2; mt++) {
#pragma unroll
        for (int ks = 0; ks < 8; ks++) {
            uint4 v = sA[((2 * w + mt) * 8 + ks) * 32 + lane];
            Afr[mt][ks][0] = v.x; Afr[mt][ks][1] = v.y;
            Afr[mt][ks][2] = v.z; Afr[mt][ks][3] = v.w;
        }
    }

    float pacc[2][2] = {{0.f, 0.f}, {0.f, 0.f}};

#pragma unroll
    for (int g4 = 0; g4 < 4; g4++) {                // n (=d) in 4 groups of 32
        float acc[2][4][4];
#pragma unroll
        for (int mt = 0; mt < 2; mt++)
#pragma unroll
            for (int nt = 0; nt < 4; nt++)
#pragma unroll
                for (int q = 0; q < 4; q++) acc[mt][nt][q] = 0.f;

#pragma unroll
        for (int ks = 0; ks < 8; ks++) {
            uint32_t Bfr[4][2];
#pragma unroll
            for (int nt = 0; nt < 4; nt++) {
                uint2 v = sB[((g4 * 4 + nt) * 8 + ks) * 32 + lane];
                Bfr[nt][0] = v.x; Bfr[nt][1] = v.y;
            }
#pragma unroll
            for (int mt = 0; mt < 2; mt++)
#pragma unroll
                for (int nt = 0; nt < 4; nt++)
                    mma16816(acc[mt][nt], Afr[mt][ks], Bfr[nt]);
        }

        // ---- group epilogue: dot with Fi (read from A-frag image of tile i)
        // ntile = g4*4 + nt = 2*(g4*2+s2) + h:  h=0 -> (x,y), h=1 -> (z,w)
#pragma unroll
        for (int mt = 0; mt < 2; mt++) {
#pragma unroll
            for (int s2 = 0; s2 < 2; s2++) {
                uint4 v = sC[((2 * w + mt) * 8 + (g4 * 2 + s2)) * 32 + lane];
                float2 lo0 = bf2_to_f2(v.x), hi0 = bf2_to_f2(v.y);
                pacc[mt][0] += acc[mt][2 * s2][0] * lo0.x + acc[mt][2 * s2][1] * lo0.y;
                pacc[mt][1] += acc[mt][2 * s2][2] * hi0.x + acc[mt][2 * s2][3] * hi0.y;
                float2 lo1 = bf2_to_f2(v.z), hi1 = bf2_to_f2(v.w);
                pacc[mt][0] += acc[mt][2 * s2 + 1][0] * lo1.x + acc[mt][2 * s2 + 1][1] * lo1.y;
                pacc[mt][1] += acc[mt][2 * s2 + 1][2] * hi1.x + acc[mt][2 * s2 + 1][3] * hi1.y;
            }
        }
    }

    // ---- quad reduce (cols live on lanes sharing lane>>2) ----
#pragma unroll
    for (int mt = 0; mt < 2; mt++)
#pragma unroll
        for (int h = 0; h < 2; h++) {
            pacc[mt][h] += __shfl_xor_sync(0xffffffffu, pacc[mt][h], 1);
            pacc[mt][h] += __shfl_xor_sync(0xffffffffu, pacc[mt][h], 2);
        }

    if ((lane & 3) == 0) {
#pragma unroll
        for (int mt = 0; mt < 2; mt++) {
#pragma unroll
            for (int h = 0; h < 2; h++) {
                int row = (2 * w + mt) * 16 + (lane >> 2) + h * 8;
                int bg = bt * 128 + row;
                float res = 0.5f * g_S[bg * F_SZ + i] * g_S[bg * F_SZ + j] + pacc[mt][h];
                out[(size_t)bg * (F_SZ * F_SZ) + i * F_SZ + j] = res;
            }
        }
    }
}

// ---------------------------------------------------------------------------
extern "C" void kernel_launch(void* const* d_in, const int* in_sizes, int n_in,
                              void* d_out, int out_size) {
    const float* feature = (const float*)d_in[0];   // [1024, 32, 128] f32
    const float* matrix  = (const float*)d_in[1];   // [32, 32, 128, 128] f32
    float* out = (float*)d_out;                     // [1024, 32, 32] f32

    cudaFuncSetAttribute(main_mma, cudaFuncAttributeMaxDynamicSharedMemorySize, 98304);

    prep_feat<<<NBT * F_SZ * 8, 256>>>(feature, (float2*)out);   // 2048 blocks
    prep_RB<<<(NPAIR * 4096) / 256, 256>>>(matrix);              // 7936 blocks
    main_mma<<<NPAIR * NBT, 128, 98304>>>(out);                  // 3968 blocks
}

// round 5
// speedup vs baseline: 1.5864x; 1.3393x over previous
#include <cuda_runtime.h>
#include <cuda_bf16.h>
#include <cstdint>

// ============================================================================
// InteractionPruning: out[b,i,j] = f_i^T Z_ij f_j,  Z = clip(sig(M)*1.2-0.1,0,1)
// Split: Z = 0.5 + R,  R = clip(0.6*tanh(M/2), -0.5, 0.5)
//   out = 0.5*S_i*S_j (fp32 exact)  +  f_i^T R f_j (bf16 mma.sync HMMA)
// v4: sC removed (Fi frags via prefetched LDG), 64KB SMEM -> 3 CTAs/SM,
//     split cp.async groups (A/B), prep_feat rewritten: coalesced + no atomics.
// ============================================================================

#define B_SZ   1024
#define F_SZ   32
#define D_SZ   128
#define NPAIR  496
#define NBT    8

// g_FA: A-frag images of feature:  [bt][f] x (mt8 x ks8 x lane32) uint4 = 32KB/tile
// g_RB: B-frag images of R:        [p]    x (nt16 x ks8 x lane32) uint2 = 32KB/pair
__device__ uint4 g_FA[NBT * F_SZ * 2048];   // 8 MB
__device__ uint4 g_RB[NPAIR * 2048];        // 15.9 MB
__device__ float g_S[B_SZ * F_SZ];          // row sums of feature

// ---------------------------------------------------------------------------
__device__ __forceinline__ void decode_pair(int p, int& i, int& j) {
    int jj = (int)((1.0f + sqrtf(1.0f + 8.0f * (float)p)) * 0.5f);
    while (jj * (jj - 1) / 2 > p) --jj;
    while ((jj + 1) * jj / 2 <= p) ++jj;
    j = jj;
    i = p - jj * (jj - 1) / 2;
}

__device__ __forceinline__ float gate_r(float m) {
    float x = 0.5f * m;
    if (fabsf(m) < 0.04f) {
        return 0.6f * (x - 0.33333334f * x * x * x);   // rel err < 1e-7
    }
    float s = 1.0f / (1.0f + __expf(-m));
    return fminf(fmaxf(1.2f * s - 0.6f, -0.5f), 0.5f);
}

__device__ __forceinline__ uint32_t pack_bf16x2(float a, float b) {
    return (uint32_t)__bfloat16_as_ushort(__float2bfloat16(a)) |
           ((uint32_t)__bfloat16_as_ushort(__float2bfloat16(b)) << 16);
}

__device__ __forceinline__ float2 bf2_to_f2(uint32_t u) {
    __nv_bfloat162 h = *reinterpret_cast<__nv_bfloat162*>(&u);
    return __bfloat1622float2(h);
}

__device__ __forceinline__ void mma16816(float* c, const uint32_t* a, const uint32_t* b) {
    asm volatile(
        "mma.sync.aligned.m16n8k16.row.col.f32.bf16.bf16.f32 "
        "{%0,%1,%2,%3}, {%4,%5,%6,%7}, {%8,%9}, {%0,%1,%2,%3};"
        : "+f"(c[0]), "+f"(c[1]), "+f"(c[2]), "+f"(c[3])
        : "r"(a[0]), "r"(a[1]), "r"(a[2]), "r"(a[3]), "r"(b[0]), "r"(b[1]));
}

#define CP_ASYNC16(dst_u32, src_ptr) \
    asm volatile("cp.async.cg.shared.global [%0], [%1], 16;" \
                 :: "r"(dst_u32), "l"(src_ptr) : "memory")
#define CP_COMMIT() asm volatile("cp.async.commit_group;" ::: "memory")
#define CP_WAIT_GROUP(n) asm volatile("cp.async.wait_group %0;" :: "n"(n) : "memory")

// ---------------------------------------------------------------------------
// prep_feat: one block per (bt, f) feature tile (128 rows x 128 cols).
//  - fully coalesced float4 loads (each warp loads a whole row per iter)
//  - row sums via warp shuffle (no atomics)
//  - smem staging (stride 68 dwords -> conflict-free frag gathers)
//  - coalesced uint4 A-fragment writes + zeroing of out
// ---------------------------------------------------------------------------
__global__ void __launch_bounds__(256) prep_feat(const float* __restrict__ feature,
                                                 float4* __restrict__ out4) {
    __shared__ uint32_t stage[128 * 68];    // bf16x2, row stride 68 dwords
    __shared__ float ssum[128];

    int tid = threadIdx.x, bid = blockIdx.x;
    int lane = tid & 31, w = tid >> 5;
    int bt = bid >> 5, f = bid & 31;

    const float4* src = reinterpret_cast<const float4*>(
        feature + ((size_t)(bt * 128) * F_SZ + f) * D_SZ);
    // row stride in float4 units: F_SZ*D_SZ/4 = 1024
#pragma unroll
    for (int it = 0; it < 16; it++) {
        int row = it * 8 + w;
        float4 v = src[(size_t)row * 1024 + lane];
        stage[row * 68 + lane * 2]     = pack_bf16x2(v.x, v.y);
        stage[row * 68 + lane * 2 + 1] = pack_bf16x2(v.z, v.w);
        float s = v.x + v.y + v.z + v.w;
#pragma unroll
        for (int o = 16; o; o >>= 1) s += __shfl_xor_sync(0xffffffffu, s, o);
        if (lane == 0) ssum[row] = s;
    }
    __syncthreads();

    if (tid < 128) g_S[(bt * 128 + tid) * F_SZ + f] = ssum[tid];

    // zero out buffer: 262144 float4 total / 256 blocks / 256 threads = 4 each
#pragma unroll
    for (int z = 0; z < 4; z++)
        out4[(size_t)bid * 1024 + z * 256 + tid] = make_float4(0.f, 0.f, 0.f, 0.f);

    // fragment generation: thread = (ks = tid>>5, lane); loop over mt
    int ks = w;
    uint4* dst = g_FA + (size_t)bid * 2048;
#pragma unroll
    for (int mt = 0; mt < 8; mt++) {
        int b0 = mt * 16 + (lane >> 2), b1 = b0 + 8;
        int c = ks * 8 + (lane & 3);
        uint4 o;
        o.x = stage[b0 * 68 + c];
        o.y = stage[b1 * 68 + c];
        o.z = stage[b0 * 68 + c + 4];
        o.w = stage[b1 * 68 + c + 4];
        dst[(mt * 8 + ks) * 32 + lane] = o;
    }
}

// ---------------------------------------------------------------------------
// prep_RB: B-fragments of R. One thread per (p,nt,ks,lane) -> uint2.
// ---------------------------------------------------------------------------
__global__ void __launch_bounds__(256) prep_RB(const float* __restrict__ matrix) {
    int g = blockIdx.x * 256 + threadIdx.x;
    int lane = g & 31, ks = (g >> 5) & 7, nt = (g >> 8) & 15;
    int p = g >> 12;
    int i, j; decode_pair(p, i, j);
    int d = nt * 8 + (lane >> 2);
    int k0 = ks * 16 + (lane & 3) * 2;
    const float2* src = reinterpret_cast<const float2*>(
        matrix + (((size_t)(i * F_SZ + j) * D_SZ + d) * D_SZ + k0));
    float2 v0 = src[0], v1 = src[4];
    uint2 o;
    o.x = pack_bf16x2(gate_r(v0.x), gate_r(v0.y));
    o.y = pack_bf16x2(gate_r(v1.x), gate_r(v1.y));
    reinterpret_cast<uint2*>(g_RB)[g] = o;
}

// ---------------------------------------------------------------------------
// Main kernel: CTA = (pair p, batch tile bt). 4 warps, 32 batch rows each.
// SMEM: sA (Fj A-frags 32KB) | sB (R B-frags 32KB) = 64KB -> 3 CTAs/SM.
// Fi epilogue frags prefetched from g_FA via coalesced LDG.
// ---------------------------------------------------------------------------
__global__ void __launch_bounds__(128, 3) main_mma(float* __restrict__ out) {
    extern __shared__ char sm[];
    int tid = threadIdx.x, w = tid >> 5, lane = tid & 31;
    int bx = blockIdx.x;
    int p = bx >> 3, bt = bx & 7;
    int i, j; decode_pair(p, i, j);

    uint32_t sb = 0;
    asm("{ .reg .u64 t; cvta.to.shared.u64 t, %1; cvt.u32.u64 %0, t; }"
        : "=r"(sb) : "l"(sm));

    const uint4* gA = g_FA + (size_t)(bt * F_SZ + j) * 2048;
    const uint4* gB = g_RB + (size_t)p * 2048;
    const uint4* gC = g_FA + (size_t)(bt * F_SZ + i) * 2048;

#pragma unroll
    for (int k = 0; k < 16; k++)
        CP_ASYNC16(sb + (uint32_t)(tid + 128 * k) * 16, (const void*)(gA + tid + 128 * k));
    CP_COMMIT();
#pragma unroll
    for (int k = 0; k < 16; k++)
        CP_ASYNC16(sb + 32768u + (uint32_t)(tid + 128 * k) * 16, (const void*)(gB + tid + 128 * k));
    CP_COMMIT();

    const uint4* sA = reinterpret_cast<const uint4*>(sm);           // [mt8][ks8][lane32]
    const uint2* sB = reinterpret_cast<const uint2*>(sm + 32768);   // [nt16][ks8][lane32]

    CP_WAIT_GROUP(1);        // A tile resident
    __syncthreads();

    // ---- load A fragments for this warp's 32 rows (mtiles 2w, 2w+1) ----
    uint32_t Afr[2][8][4];
#pragma unroll
    for (int mt = 0; mt < 2; mt++) {
#pragma unroll
        for (int ks = 0; ks < 8; ks++) {
            uint4 v = sA[((2 * w + mt) * 8 + ks) * 32 + lane];
            Afr[mt][ks][0] = v.x; Afr[mt][ks][1] = v.y;
            Afr[mt][ks][2] = v.z; Afr[mt][ks][3] = v.w;
        }
    }

    CP_WAIT_GROUP(0);        // B tile resident
    __syncthreads();

    float pacc[2][2] = {{0.f, 0.f}, {0.f, 0.f}};

#pragma unroll
    for (int g4 = 0; g4 < 4; g4++) {                // n (=d) in 4 groups of 32
        // prefetch Fi epilogue frags for this group (coalesced LDG.128, L2-hit)
        uint4 cf[2][2];
#pragma unroll
        for (int mt = 0; mt < 2; mt++)
#pragma unroll
            for (int s2 = 0; s2 < 2; s2++)
                cf[mt][s2] = gC[((2 * w + mt) * 8 + (g4 * 2 + s2)) * 32 + lane];

        float acc[2][4][4];
#pragma unroll
        for (int mt = 0; mt < 2; mt++)
#pragma unroll
            for (int nt = 0; nt < 4; nt++)
#pragma unroll
                for (int q = 0; q < 4; q++) acc[mt][nt][q] = 0.f;

#pragma unroll
        for (int ks = 0; ks < 8; ks++) {
            uint32_t Bfr[4][2];
#pragma unroll
            for (int nt = 0; nt < 4; nt++) {
                uint2 v = sB[((g4 * 4 + nt) * 8 + ks) * 32 + lane];
                Bfr[nt][0] = v.x; Bfr[nt][1] = v.y;
            }
#pragma unroll
            for (int mt = 0; mt < 2; mt++)
#pragma unroll
                for (int nt = 0; nt < 4; nt++)
                    mma16816(acc[mt][nt], Afr[mt][ks], Bfr[nt]);
        }

        // ---- group epilogue: dot with Fi frags ----
        // ntile = g4*4 + 2*s2 + h:  h=0 -> (x,y), h=1 -> (z,w)
#pragma unroll
        for (int mt = 0; mt < 2; mt++) {
#pragma unroll
            for (int s2 = 0; s2 < 2; s2++) {
                uint4 v = cf[mt][s2];
                float2 lo0 = bf2_to_f2(v.x), hi0 = bf2_to_f2(v.y);
                pacc[mt][0] += acc[mt][2 * s2][0] * lo0.x + acc[mt][2 * s2][1] * lo0.y;
                pacc[mt][1] += acc[mt][2 * s2][2] * hi0.x + acc[mt][2 * s2][3] * hi0.y;
                float2 lo1 = bf2_to_f2(v.z), hi1 = bf2_to_f2(v.w);
                pacc[mt][0] += acc[mt][2 * s2 + 1][0] * lo1.x + acc[mt][2 * s2 + 1][1] * lo1.y;
                pacc[mt][1] += acc[mt][2 * s2 + 1][2] * hi1.x + acc[mt][2 * s2 + 1][3] * hi1.y;
            }
        }
    }

    // ---- quad reduce ----
#pragma unroll
    for (int mt = 0; mt < 2; mt++)
#pragma unroll
        for (int h = 0; h < 2; h++) {
            pacc[mt][h] += __shfl_xor_sync(0xffffffffu, pacc[mt][h], 1);
            pacc[mt][h] += __shfl_xor_sync(0xffffffffu, pacc[mt][h], 2);
        }

    if ((lane & 3) == 0) {
#pragma unroll
        for (int mt = 0; mt < 2; mt++) {
#pragma unroll
            for (int h = 0; h < 2; h++) {
                int row = (2 * w + mt) * 16 + (lane >> 2) + h * 8;
                int bg = bt * 128 + row;
                float res = 0.5f * g_S[bg * F_SZ + i] * g_S[bg * F_SZ + j] + pacc[mt][h];
                out[(size_t)bg * (F_SZ * F_SZ) + i * F_SZ + j] = res;
            }
        }
    }
}

// ---------------------------------------------------------------------------
extern "C" void kernel_launch(void* const* d_in, const int* in_sizes, int n_in,
                              void* d_out, int out_size) {
    const float* feature = (const float*)d_in[0];   // [1024, 32, 128] f32
    const float* matrix  = (const float*)d_in[1];   // [32, 32, 128, 128] f32
    float* out = (float*)d_out;                     // [1024, 32, 32] f32

    cudaFuncSetAttribute(main_mma, cudaFuncAttributeMaxDynamicSharedMemorySize, 65536);

    prep_feat<<<NBT * F_SZ, 256>>>(feature, (float4*)out);       // 256 blocks
    prep_RB<<<(NPAIR * 4096) / 256, 256>>>(matrix);              // 7936 blocks
    main_mma<<<NPAIR * NBT, 128, 65536>>>(out);                  // 3968 blocks
}